// round 4
// baseline (speedup 1.0000x reference)
#include <cuda_runtime.h>

// out[i,j] = x0[i,j] * (x_l[i] . w) + b[j] + x_l[i,j]
// B = 65536 rows, DIM = 1024.
// One block per row, 256 threads, float4 per thread.
// R1 structure (best DRAM% so far) + early x_0/b loads so the reduction
// barrier overlaps the second stream's DRAM latency. NO cache-op hints --
// the __ldcs/__stcs variant measurably lowered DRAM throughput.

#define DIM 1024
#define THREADS 256  // DIM/4

__global__ __launch_bounds__(THREADS) void dcn_kernel(
    const float* __restrict__ x_l,
    const float* __restrict__ x_0,
    const float* __restrict__ w,
    const float* __restrict__ b,
    float* __restrict__ out)
{
    const int row = blockIdx.x;
    const int t   = threadIdx.x;
    const size_t base4 = (size_t)row * (DIM / 4);

    const float4* __restrict__ xl4 = reinterpret_cast<const float4*>(x_l);
    const float4* __restrict__ x04 = reinterpret_cast<const float4*>(x_0);
    const float4* __restrict__ w4  = reinterpret_cast<const float4*>(w);
    const float4* __restrict__ b4  = reinterpret_cast<const float4*>(b);
    float4* __restrict__ out4      = reinterpret_cast<float4*>(out);

    // Front-batch all loads: both DRAM streams in flight together (MLP_p1=2),
    // w/b are 4 KB broadcasts that stay L1/L2 resident.
    float4 a  = xl4[base4 + t];
    float4 c  = x04[base4 + t];
    float4 wv = w4[t];
    float4 bv = b4[t];

    // Partial dot product.
    float local = a.x * wv.x + a.y * wv.y + a.z * wv.z + a.w * wv.w;

    // Warp butterfly reduce.
    #pragma unroll
    for (int off = 16; off > 0; off >>= 1)
        local += __shfl_xor_sync(0xffffffffu, local, off);

    __shared__ float warpsum[THREADS / 32];
    if ((t & 31) == 0) warpsum[t >> 5] = local;
    __syncthreads();

    float s = 0.0f;
    #pragma unroll
    for (int i = 0; i < THREADS / 32; i++) s += warpsum[i];

    // Pure-register epilogue.
    float4 o;
    o.x = fmaf(c.x, s, bv.x + a.x);
    o.y = fmaf(c.y, s, bv.y + a.y);
    o.z = fmaf(c.z, s, bv.z + a.z);
    o.w = fmaf(c.w, s, bv.w + a.w);
    out4[base4 + t] = o;
}

extern "C" void kernel_launch(void* const* d_in, const int* in_sizes, int n_in,
                              void* d_out, int out_size)
{
    const float* x_l = (const float*)d_in[0];
    const float* x_0 = (const float*)d_in[1];
    const float* w   = (const float*)d_in[2];
    const float* b   = (const float*)d_in[3];
    float* out       = (float*)d_out;

    const int B = in_sizes[0] / DIM;  // 65536
    dcn_kernel<<<B, THREADS>>>(x_l, x_0, w, b, out);
}